// round 1
// baseline (speedup 1.0000x reference)
#include <cuda_runtime.h>
#include <math.h>

#define KP 32      // particles
#define BB 256     // batch
#define TT 32      // time steps
#define DH 128
#define EH 128
#define NG 512     // 4*DH

// ---------------- scratch (device globals; no allocation) ----------------
__device__ float g_E1[BB * TT * EH];          // enc @ W1_e + b1
__device__ float g_H[2][KP * BB * DH];        // ping-pong hiddens
__device__ float g_C[2][KP * BB * DH];        // ping-pong cells
__device__ float g_yt[BB];                    // y_tilde (F=1)
__device__ float g_sp[BB * DH];               // softplus(var)
__device__ float g_ctx[BB * EH];              // context (last step used at end)
__device__ float g_proj[KP * BB];             // h2 . fcdec_W + b
__device__ float g_pdfdot[KP * BB];           // h2 . pdf_W[0:128]
__device__ int   g_srcH[KP * BB];             // composed resample index for h
__device__ int   g_srcC[KP * BB];             // resample index for c (unsorted!)

__device__ __forceinline__ float sigm(float x) { return 1.0f / (1.0f + expf(-x)); }
__device__ __forceinline__ float softplusf(float x) {
    // jax.nn.softplus = logaddexp(x,0) = max(x,0) + log1p(exp(-|x|))
    return fmaxf(x, 0.0f) + log1pf(expf(-fabsf(x)));
}

// ---------------- K0: E1[b,t,h] = sum_e enc[b,t,e]*W1[256+e,h] + b1[h] ----
__global__ void k0_e1(const float* __restrict__ enc, const float* __restrict__ W1,
                      const float* __restrict__ b1)
{
    int b = blockIdx.x, tid = threadIdx.x;
    __shared__ float enc_s[TT * EH];     // 16KB
    __shared__ float w1_s[16 * 128];     // 8KB
    for (int idx = tid; idx < TT * EH; idx += 256)
        enc_s[idx] = enc[b * TT * EH + idx];
    int tq = tid >> 7;       // 0..1 : which half of t'
    int h  = tid & 127;
    float acc[16];
#pragma unroll
    for (int i = 0; i < 16; i++) acc[i] = 0.0f;
    for (int ec = 0; ec < 8; ec++) {
        __syncthreads();
        for (int idx = tid; idx < 16 * 128; idx += 256)
            w1_s[idx] = W1[(256 + ec * 16) * 128 + idx];
        __syncthreads();
#pragma unroll 4
        for (int jj = 0; jj < 16; jj++) {
            float wv = w1_s[jj * 128 + h];
            int e = ec * 16 + jj;
#pragma unroll
            for (int i = 0; i < 16; i++)
                acc[i] += enc_s[(tq * 16 + i) * 128 + e] * wv;
        }
    }
    float bv = b1[h];
#pragma unroll
    for (int i = 0; i < 16; i++)
        g_E1[(b * TT + tq * 16 + i) * 128 + h] = acc[i] + bv;
}

// ---------------- K1: per-b attention / context / y_tilde / var ----------
__global__ void k1_attn(int t, const float* __restrict__ enc,
                        const float* __restrict__ yprev,
                        const float* __restrict__ W1,
                        const float* __restrict__ W2, const float* __restrict__ b2,
                        const float* __restrict__ fcW, const float* __restrict__ fcb,
                        const float* __restrict__ varW, const float* __restrict__ varb)
{
    int b = blockIdx.x, tid = threadIdx.x;
    __shared__ float hbar[DH], cbar[DH], hcp[DH], hcp2[DH];
    __shared__ float a_s[TT], beta_s[TT], ctx_s[EH];
    __shared__ float yt_s;
    int rb = (t - 1) & 1;

    // hbar/cbar via resample-index gather
    if (tid < 128) {
        float s = 0.0f;
        if (t > 0)
            for (int p = 0; p < KP; p++) {
                int row = g_srcH[p * BB + b];
                s += g_H[rb][(row * BB + b) * DH + tid];
            }
        hbar[tid] = s * (1.0f / 32.0f);
    } else {
        int d = tid - 128;
        float s = 0.0f;
        if (t > 0)
            for (int p = 0; p < KP; p++) {
                int row = g_srcC[p * BB + b];
                s += g_C[rb][(row * BB + b) * DH + d];
            }
        cbar[d] = s * (1.0f / 32.0f);
    }
    __syncthreads();

    // hc_proj = hbar@W1_h + cbar@W1_c
    if (tid < 128) {
        float s = 0.0f;
        for (int j = 0; j < 128; j++) s += hbar[j] * W1[j * 128 + tid];
        hcp[tid] = s;
    } else {
        int h = tid - 128;
        float s = 0.0f;
        for (int j = 0; j < 128; j++) s += cbar[j] * W1[(128 + j) * 128 + h];
        hcp2[h] = s;
    }
    __syncthreads();
    if (tid < 128) hcp[tid] += hcp2[tid];
    __syncthreads();

    // attention logits: a[t'] = sum_h tanh(hcp+E1) * W2 + b2
    int w = tid >> 5, lane = tid & 31;
#pragma unroll
    for (int q = 0; q < 4; q++) {
        int tp = w * 4 + q;
        const float* e1 = &g_E1[(b * TT + tp) * 128];
        float acc = 0.0f;
        for (int hh = lane; hh < 128; hh += 32)
            acc += tanhf(hcp[hh] + e1[hh]) * W2[hh];
        for (int off = 16; off; off >>= 1) acc += __shfl_down_sync(0xffffffffu, acc, off);
        if (lane == 0) a_s[tp] = acc + b2[0];
    }
    __syncthreads();

    // softmax over T
    if (w == 0) {
        float v = a_s[lane];
        float m = v;
        for (int off = 16; off; off >>= 1) m = fmaxf(m, __shfl_xor_sync(0xffffffffu, m, off));
        float e = expf(v - m);
        float s = e;
        for (int off = 16; off; off >>= 1) s += __shfl_xor_sync(0xffffffffu, s, off);
        beta_s[lane] = e / s;
    }
    __syncthreads();

    // context
    if (tid < 128) {
        float acc = 0.0f;
        for (int tp = 0; tp < TT; tp++)
            acc += beta_s[tp] * enc[(b * TT + tp) * 128 + tid];
        ctx_s[tid] = acc;
        g_ctx[b * 128 + tid] = acc;   // only last step's value is consumed
    }
    __syncthreads();

    // y_tilde (scalar, F=1)
    if (w == 0) {
        float acc = 0.0f;
        for (int e = lane; e < 128; e += 32) acc += ctx_s[e] * fcW[e];
        for (int off = 16; off; off >>= 1) acc += __shfl_down_sync(0xffffffffu, acc, off);
        if (lane == 0) {
            float yt = acc + yprev[b * TT + t] * fcW[128] + fcb[0];
            yt_s = yt;
            g_yt[b] = yt;
        }
    }
    __syncthreads();

    // var -> softplus   var[d] = yt*varW[0,d] + hbar@varW[1:,d] + varb[d]
    if (tid < 128) {
        float v = yt_s * varW[tid] + varb[tid];
        for (int j = 0; j < 128; j++)
            v += hbar[j] * varW[(1 + j) * 128 + tid];
        g_sp[b * 128 + tid] = softplusf(v);
    }
}

// ---------------- K2: LSTM step + reparam + proj/pdf dots -----------------
__global__ void __launch_bounds__(256) k2_lstm(
        int t, const float* __restrict__ Whh, const float* __restrict__ Wih,
        const float* __restrict__ bih, const float* __restrict__ bhh,
        const float* __restrict__ eps,
        const float* __restrict__ fcdW, const float* __restrict__ fcdb,
        const float* __restrict__ pdfW)
{
    int b = blockIdx.x, tid = threadIdx.x;
    __shared__ __align__(16) float h_s[128 * 36];   // [j][k] padded, 18.4KB
    __shared__ __align__(16) float w_s[8 * 512];    // 16KB chunk of W_hh
    __shared__ float red_p[KP][2], red_q[KP][2];
    int rb = (t - 1) & 1, wb = t & 1;

    int kq = tid >> 6;     // 0..3  (k block of 8)
    int dq = tid & 63;     // 0..63 (d pair)
    int d0 = dq * 2;

    float acc[8][8];       // [k in block][{i0,i1,f0,f1,g0,g1,o0,o1}]
#pragma unroll
    for (int i = 0; i < 8; i++)
#pragma unroll
        for (int c = 0; c < 8; c++) acc[i][c] = 0.0f;

    if (t > 0) {
        for (int idx = tid; idx < KP * 128; idx += 256) {
            int k = idx >> 7, j = idx & 127;
            int row = g_srcH[k * BB + b];
            h_s[j * 36 + k] = g_H[rb][(row * BB + b) * DH + j];
        }
        __syncthreads();
        for (int cj = 0; cj < 16; cj++) {
            for (int idx = tid; idx < 8 * 512; idx += 256)
                w_s[idx] = Whh[cj * 8 * 512 + idx];
            __syncthreads();
#pragma unroll
            for (int jj = 0; jj < 8; jj++) {
                const float* hr = &h_s[(cj * 8 + jj) * 36 + kq * 8];
                float4 ha = *(const float4*)hr;
                float4 hb = *(const float4*)(hr + 4);
                float hv[8] = {ha.x, ha.y, ha.z, ha.w, hb.x, hb.y, hb.z, hb.w};
                const float* wr = &w_s[jj * 512];
                float2 wi = *(const float2*)(wr + d0);
                float2 wf = *(const float2*)(wr + 128 + d0);
                float2 wg = *(const float2*)(wr + 256 + d0);
                float2 wo = *(const float2*)(wr + 384 + d0);
#pragma unroll
                for (int i = 0; i < 8; i++) {
                    acc[i][0] += hv[i] * wi.x;  acc[i][1] += hv[i] * wi.y;
                    acc[i][2] += hv[i] * wf.x;  acc[i][3] += hv[i] * wf.y;
                    acc[i][4] += hv[i] * wg.x;  acc[i][5] += hv[i] * wg.y;
                    acc[i][6] += hv[i] * wo.x;  acc[i][7] += hv[i] * wo.y;
                }
            }
            __syncthreads();
        }
    }

    // x-term + biases for this thread's 8 gate columns
    float yt = g_yt[b];
    float2 spv = *(const float2*)&g_sp[b * 128 + d0];
    float xb[8];
#pragma unroll
    for (int g4 = 0; g4 < 4; g4++)
#pragma unroll
        for (int dd = 0; dd < 2; dd++) {
            int col = g4 * 128 + d0 + dd;
            xb[g4 * 2 + dd] = yt * Wih[col] + bih[col] + bhh[col];
        }

    float fcd0 = fcdW[d0], fcd1 = fcdW[d0 + 1];
    float pw0 = pdfW[d0],  pw1 = pdfW[d0 + 1];
    float pacc[8], qacc[8];
#pragma unroll
    for (int i = 0; i < 8; i++) {
        int k = kq * 8 + i;
        float cp0 = 0.0f, cp1 = 0.0f;
        if (t > 0) {
            int crow = g_srcC[k * BB + b];
            float2 cv = *(const float2*)&g_C[rb][(crow * BB + b) * DH + d0];
            cp0 = cv.x; cp1 = cv.y;
        }
        float ii0 = acc[i][0] + xb[0], ii1 = acc[i][1] + xb[1];
        float ff0 = acc[i][2] + xb[2], ff1 = acc[i][3] + xb[3];
        float gg0 = acc[i][4] + xb[4], gg1 = acc[i][5] + xb[5];
        float oo0 = acc[i][6] + xb[6], oo1 = acc[i][7] + xb[7];
        float c20 = sigm(ff0) * cp0 + sigm(ii0) * tanhf(gg0);
        float c21 = sigm(ff1) * cp1 + sigm(ii1) * tanhf(gg1);
        float h20 = sigm(oo0) * tanhf(c20);
        float h21 = sigm(oo1) * tanhf(c21);
        float2 ev = *(const float2*)&eps[(size_t)((t * KP + k) * BB + b) * DH + d0];
        h20 += ev.x * spv.x;
        h21 += ev.y * spv.y;
        int o = (k * BB + b) * DH + d0;
        *(float2*)&g_H[wb][o] = make_float2(h20, h21);
        *(float2*)&g_C[wb][o] = make_float2(c20, c21);
        pacc[i] = h20 * fcd0 + h21 * fcd1;
        qacc[i] = h20 * pw0 + h21 * pw1;
    }
    // reduce pacc/qacc over the 64 threads sharing kq (2 warps)
#pragma unroll
    for (int i = 0; i < 8; i++) {
        float p = pacc[i], q = qacc[i];
        for (int off = 16; off; off >>= 1) {
            p += __shfl_down_sync(0xffffffffu, p, off);
            q += __shfl_down_sync(0xffffffffu, q, off);
        }
        if ((tid & 31) == 0) {
            red_p[kq * 8 + i][(tid >> 5) & 1] = p;
            red_q[kq * 8 + i][(tid >> 5) & 1] = q;
        }
    }
    __syncthreads();
    if (tid < KP) {
        g_proj[tid * BB + b]   = red_p[tid][0] + red_p[tid][1] + fcdb[0];
        g_pdfdot[tid * BB + b] = red_q[tid][0] + red_q[tid][1];
    }
}

// ---------------- K3: sort / weights / gumbel-max resample ----------------
// One CTA per 32-b block (the torch view(-1,K) normalization group).
__global__ void k3_resample(int t, const float* __restrict__ gumbel,
                            const float* __restrict__ pdfW,
                            const float* __restrict__ pdfb)
{
    int blk = blockIdx.x;          // 0..7
    int tid = threadIdx.x;         // 1024
    __shared__ float proj_s[32][33];
    __shared__ int   order_s[32][33];
    __shared__ float p_s[32][33];   // [slot][b_local]
    __shared__ float lw_s[32][33];  // [b_local][slot]

    {   // load proj (coalesced), store transposed
        int kk = tid >> 5, bb = tid & 31;
        proj_s[bb][kk] = g_proj[kk * BB + blk * 32 + bb];
    }
    __syncthreads();
    {   // stable ascending rank (matches jnp.argsort)
        int bl = tid >> 5, k = tid & 31;
        float v = proj_s[bl][k];
        int r = 0;
#pragma unroll
        for (int kp = 0; kp < 32; kp++) {
            float u = proj_s[bl][kp];
            r += (u < v) || (u == v && kp < k);
        }
        order_s[bl][r] = k;
    }
    __syncthreads();
    float pwy = pdfW[128], pb = pdfb[0];
    {   // p[slot,b] = exp(logpdf of sorted slot)
        int slot = tid >> 5, bb = tid & 31;
        int bg = blk * 32 + bb;
        int k0 = order_s[bb][slot];
        float lp = g_pdfdot[k0 * BB + bg] + g_yt[bg] * pwy + pb;
        p_s[slot][bb] = expf(lp);
    }
    __syncthreads();
    {   // Z over the 32-b block per slot; lw = log(w+1e-30)
        int slot = tid >> 5, bb = tid & 31;
        float v = p_s[slot][bb];
        float s = v;
        for (int off = 16; off; off >>= 1) s += __shfl_xor_sync(0xffffffffu, s, off);
        lw_s[bb][slot] = logf(v / s + 1e-30f);
    }
    __syncthreads();
    {   // gumbel argmax (first occurrence), compose indices
        int bb = tid >> 5, p = tid & 31;
        int bg = blk * 32 + bb;
        const float* g = &gumbel[(((size_t)t * BB + bg) * KP + p) * KP];
        float best = -3.0e38f;
        int bi = 0;
#pragma unroll
        for (int kp = 0; kp < 32; kp++) {
            float v = lw_s[bb][kp] + g[kp];
            if (v > best) { best = v; bi = kp; }
        }
        g_srcH[p * BB + bg] = order_s[bb][bi];  // h was sorted before selection
        g_srcC[p * BB + bg] = bi;               // c was NOT sorted (torch quirk)
    }
}

// ---------------- K4: final projections -----------------------------------
__global__ void k4_out(const float* __restrict__ fcdW, const float* __restrict__ fcdb,
                       const float* __restrict__ fceW, const float* __restrict__ fceb,
                       float* __restrict__ out)
{
    int b = blockIdx.x * 8 + (threadIdx.x >> 5);
    int lane = threadIdx.x & 31;
    float a1 = 0.0f, a2 = 0.0f;
    for (int d = lane; d < 128; d += 32) {
        float hm = 0.0f;
        for (int p = 0; p < KP; p++) {
            int row = g_srcH[p * BB + b];
            hm += g_H[1][(row * BB + b) * DH + d];   // (T-1)&1 == 1
        }
        a1 += (hm * (1.0f / 32.0f)) * fcdW[d];
        a2 += g_ctx[b * 128 + d] * fceW[d];
    }
    for (int off = 16; off; off >>= 1) {
        a1 += __shfl_down_sync(0xffffffffu, a1, off);
        a2 += __shfl_down_sync(0xffffffffu, a2, off);
    }
    if (lane == 0) out[b] = a1 + fcdb[0] + a2 + fceb[0];
}

// ---------------- launch ---------------------------------------------------
extern "C" void kernel_launch(void* const* d_in, const int* in_sizes, int n_in,
                              void* d_out, int out_size)
{
    const float* enc   = (const float*)d_in[0];
    const float* yprev = (const float*)d_in[1];
    const float* eps   = (const float*)d_in[2];
    const float* gum   = (const float*)d_in[3];
    const float* W1    = (const float*)d_in[4];
    const float* b1    = (const float*)d_in[5];
    const float* W2    = (const float*)d_in[6];
    const float* b2    = (const float*)d_in[7];
    const float* Wih   = (const float*)d_in[8];
    const float* Whh   = (const float*)d_in[9];
    const float* bih   = (const float*)d_in[10];
    const float* bhh   = (const float*)d_in[11];
    const float* fcW   = (const float*)d_in[12];
    const float* fcb   = (const float*)d_in[13];
    const float* fcdW  = (const float*)d_in[14];
    const float* fcdb  = (const float*)d_in[15];
    const float* fceW  = (const float*)d_in[16];
    const float* fceb  = (const float*)d_in[17];
    const float* varW  = (const float*)d_in[18];
    const float* varb  = (const float*)d_in[19];
    const float* pdfW  = (const float*)d_in[20];
    const float* pdfb  = (const float*)d_in[21];
    float* out = (float*)d_out;

    k0_e1<<<BB, 256>>>(enc, W1, b1);
    for (int t = 0; t < TT; t++) {
        k1_attn<<<BB, 256>>>(t, enc, yprev, W1, W2, b2, fcW, fcb, varW, varb);
        k2_lstm<<<BB, 256>>>(t, Whh, Wih, bih, bhh, eps, fcdW, fcdb, pdfW);
        k3_resample<<<8, 1024>>>(t, gum, pdfW, pdfb);
    }
    k4_out<<<BB / 8, 256>>>(fcdW, fcdb, fceW, fceb, out);
}

// round 2
// speedup vs baseline: 1.0793x; 1.0793x over previous
#include <cuda_runtime.h>
#include <math.h>

#define KP 32      // particles
#define BB 256     // batch
#define TT 32      // time steps
#define DH 128
#define EH 128

typedef unsigned long long ull;

// ---------------- scratch (device globals; no allocation) ----------------
__device__ float g_E1[BB * TT * EH];          // enc @ W1_e + b1
__device__ float g_H[2][KP * BB * DH];        // ping-pong hiddens
__device__ float g_C[2][KP * BB * DH];        // ping-pong cells
__device__ float g_yt[BB];                    // y_tilde (F=1)
__device__ float g_ctx[BB * EH];              // context (last step used at end)
__device__ float g_proj[KP * BB];             // h2 . fcdec_W + b
__device__ float g_pdfdot[KP * BB];           // h2 . pdf_W[0:128]
__device__ int   g_srcH[KP * BB];             // composed resample index for h
__device__ int   g_srcC[KP * BB];             // resample index for c (unsorted!)

__device__ __forceinline__ float sigm(float x) { return 1.0f / (1.0f + expf(-x)); }
__device__ __forceinline__ float softplusf(float x) {
    return fmaxf(x, 0.0f) + log1pf(expf(-fabsf(x)));
}
__device__ __forceinline__ void fma2(ull& d, ull a, ull b) {
    asm("fma.rn.f32x2 %0, %1, %2, %0;" : "+l"(d) : "l"(a), "l"(b));
}
__device__ __forceinline__ float2 unpk(ull v) {
    float2 f; asm("mov.b64 {%0,%1}, %2;" : "=f"(f.x), "=f"(f.y) : "l"(v)); return f;
}
__device__ __forceinline__ ull pk(float lo, float hi) {
    ull u; asm("mov.b64 %0, {%1,%2};" : "=l"(u) : "f"(lo), "f"(hi)); return u;
}

// ---------------- K0: E1[b,t,h] = sum_e enc[b,t,e]*W1[256+e,h] + b1[h] ----
__global__ void k0_e1(const float* __restrict__ enc, const float* __restrict__ W1,
                      const float* __restrict__ b1)
{
    int b = blockIdx.x, tid = threadIdx.x;
    __shared__ float enc_s[TT * EH];
    __shared__ float w1_s[16 * 128];
    for (int idx = tid; idx < TT * EH; idx += 256)
        enc_s[idx] = enc[b * TT * EH + idx];
    int tq = tid >> 7;
    int h  = tid & 127;
    float acc[16];
#pragma unroll
    for (int i = 0; i < 16; i++) acc[i] = 0.0f;
    for (int ec = 0; ec < 8; ec++) {
        __syncthreads();
        for (int idx = tid; idx < 16 * 128; idx += 256)
            w1_s[idx] = W1[(256 + ec * 16) * 128 + idx];
        __syncthreads();
#pragma unroll 4
        for (int jj = 0; jj < 16; jj++) {
            float wv = w1_s[jj * 128 + h];
            int e = ec * 16 + jj;
#pragma unroll
            for (int i = 0; i < 16; i++)
                acc[i] += enc_s[(tq * 16 + i) * 128 + e] * wv;
        }
    }
    float bv = b1[h];
#pragma unroll
    for (int i = 0; i < 16; i++)
        g_E1[(b * TT + tq * 16 + i) * 128 + h] = acc[i] + bv;
}

// ---------------- kA: fused attention + var + LSTM + reparam + dots -------
__global__ void __launch_bounds__(256) kA_step(
        int t, const float* __restrict__ enc, const float* __restrict__ yprev,
        const float* __restrict__ W1, const float* __restrict__ W2,
        const float* __restrict__ b2, const float* __restrict__ fcW,
        const float* __restrict__ fcb, const float* __restrict__ varW,
        const float* __restrict__ varb,
        const float* __restrict__ Whh, const float* __restrict__ Wih,
        const float* __restrict__ bih, const float* __restrict__ bhh,
        const float* __restrict__ eps,
        const float* __restrict__ fcdW, const float* __restrict__ fcdb,
        const float* __restrict__ pdfW)
{
    int b = blockIdx.x, tid = threadIdx.x;
    __shared__ float hbar[DH], cbar[DH], hcp[DH], hcp2[DH];
    __shared__ float a_s[TT], beta_s[TT], ctx_s[EH], sp_s[DH];
    __shared__ float yt_sh;
    __shared__ __align__(16) float h_s[128 * 36];       // [j][k], padded
    __shared__ __align__(16) ull w_s2[4 * 512];         // packed (w,w) chunk of W_hh
    __shared__ float red_p[KP][2], red_q[KP][2];
    int rb = (t - 1) & 1, wb = t & 1;

    // ---- phase 1: hbar/cbar via resample gather ----
    if (tid < 128) {
        float s = 0.0f;
        if (t > 0)
            for (int p = 0; p < KP; p++) {
                int row = g_srcH[p * BB + b];
                s += g_H[rb][(row * BB + b) * DH + tid];
            }
        hbar[tid] = s * (1.0f / 32.0f);
    } else {
        int d = tid - 128;
        float s = 0.0f;
        if (t > 0)
            for (int p = 0; p < KP; p++) {
                int row = g_srcC[p * BB + b];
                s += g_C[rb][(row * BB + b) * DH + d];
            }
        cbar[d] = s * (1.0f / 32.0f);
    }
    __syncthreads();

    // hc_proj = hbar@W1_h + cbar@W1_c
    if (tid < 128) {
        float s = 0.0f;
        for (int j = 0; j < 128; j++) s += hbar[j] * W1[j * 128 + tid];
        hcp[tid] = s;
    } else {
        int h = tid - 128;
        float s = 0.0f;
        for (int j = 0; j < 128; j++) s += cbar[j] * W1[(128 + j) * 128 + h];
        hcp2[h] = s;
    }
    __syncthreads();
    if (tid < 128) hcp[tid] += hcp2[tid];
    __syncthreads();

    // attention logits
    int w = tid >> 5, lane = tid & 31;
#pragma unroll
    for (int q = 0; q < 4; q++) {
        int tp = w * 4 + q;
        const float* e1 = &g_E1[(b * TT + tp) * 128];
        float acc = 0.0f;
        for (int hh = lane; hh < 128; hh += 32)
            acc += tanhf(hcp[hh] + e1[hh]) * W2[hh];
        for (int off = 16; off; off >>= 1) acc += __shfl_down_sync(0xffffffffu, acc, off);
        if (lane == 0) a_s[tp] = acc + b2[0];
    }
    __syncthreads();

    // softmax over T
    if (w == 0) {
        float v = a_s[lane];
        float m = v;
        for (int off = 16; off; off >>= 1) m = fmaxf(m, __shfl_xor_sync(0xffffffffu, m, off));
        float e = expf(v - m);
        float s = e;
        for (int off = 16; off; off >>= 1) s += __shfl_xor_sync(0xffffffffu, s, off);
        beta_s[lane] = e / s;
    }
    __syncthreads();

    // context
    if (tid < 128) {
        float acc = 0.0f;
        for (int tp = 0; tp < TT; tp++)
            acc += beta_s[tp] * enc[(b * TT + tp) * 128 + tid];
        ctx_s[tid] = acc;
        g_ctx[b * 128 + tid] = acc;
    }
    __syncthreads();

    // y_tilde (scalar)
    if (w == 0) {
        float acc = 0.0f;
        for (int e = lane; e < 128; e += 32) acc += ctx_s[e] * fcW[e];
        for (int off = 16; off; off >>= 1) acc += __shfl_down_sync(0xffffffffu, acc, off);
        if (lane == 0) {
            float yt = acc + yprev[b * TT + t] * fcW[128] + fcb[0];
            yt_sh = yt;
            g_yt[b] = yt;
        }
    }
    __syncthreads();

    // var -> softplus (shared only)
    if (tid < 128) {
        float v = yt_sh * varW[tid] + varb[tid];
        for (int j = 0; j < 128; j++)
            v += hbar[j] * varW[(1 + j) * 128 + tid];
        sp_s[tid] = softplusf(v);
    }
    __syncthreads();

    // ---- phase 2: LSTM GEMM with packed f32x2 FMA ----
    int kq = tid >> 6;     // 0..3 (block of 8 particles)
    int dq = tid & 63;
    int d0 = dq * 2;

    // acc2[kpair][col]: kpair i covers k = kq*8 + 2i{,+1}; col = gate*2 + dd
    ull acc2[4][8];
#pragma unroll
    for (int i = 0; i < 4; i++)
#pragma unroll
        for (int c = 0; c < 8; c++) acc2[i][c] = 0ull;

    if (t > 0) {
        for (int idx = tid; idx < KP * 128; idx += 256) {
            int k = idx >> 7, j = idx & 127;
            int row = g_srcH[k * BB + b];
            h_s[j * 36 + k] = g_H[rb][(row * BB + b) * DH + j];
        }
        __syncthreads();
        for (int cj = 0; cj < 32; cj++) {
            // pack 4 rows of W_hh as (w,w) broadcast pairs
            for (int idx = tid; idx < 4 * 512; idx += 256) {
                float wv = Whh[cj * 4 * 512 + idx];
                w_s2[idx] = pk(wv, wv);
            }
            __syncthreads();
#pragma unroll
            for (int jj = 0; jj < 4; jj++) {
                int j = cj * 4 + jj;
                const ull* hr = (const ull*)&h_s[j * 36 + kq * 8];
                ull h0 = hr[0], h1 = hr[1], h2 = hr[2], h3 = hr[3];
                const ull* wr = &w_s2[jj * 512];
                ull wv[8];
#pragma unroll
                for (int g = 0; g < 4; g++) {
                    wv[2 * g]     = wr[g * 128 + d0];
                    wv[2 * g + 1] = wr[g * 128 + d0 + 1];
                }
#pragma unroll
                for (int c = 0; c < 8; c++) {
                    fma2(acc2[0][c], h0, wv[c]);
                    fma2(acc2[1][c], h1, wv[c]);
                    fma2(acc2[2][c], h2, wv[c]);
                    fma2(acc2[3][c], h3, wv[c]);
                }
            }
            __syncthreads();
        }
    }

    // x-term + biases for this thread's 8 gate columns
    float yt = yt_sh;
    float2 spv = *(const float2*)&sp_s[d0];
    float xb[8];
#pragma unroll
    for (int g4 = 0; g4 < 4; g4++)
#pragma unroll
        for (int dd = 0; dd < 2; dd++) {
            int col = g4 * 128 + d0 + dd;
            xb[g4 * 2 + dd] = yt * Wih[col] + bih[col] + bhh[col];
        }

    float fcd0 = fcdW[d0], fcd1 = fcdW[d0 + 1];
    float pw0 = pdfW[d0],  pw1 = pdfW[d0 + 1];
    float pacc[8], qacc[8];
#pragma unroll
    for (int i = 0; i < 4; i++) {
        float2 gi = unpk(acc2[i][0]), gi1 = unpk(acc2[i][1]);
        float2 gf = unpk(acc2[i][2]), gf1 = unpk(acc2[i][3]);
        float2 gg = unpk(acc2[i][4]), gg1 = unpk(acc2[i][5]);
        float2 go = unpk(acc2[i][6]), go1 = unpk(acc2[i][7]);
#pragma unroll
        for (int s = 0; s < 2; s++) {
            int k = kq * 8 + 2 * i + s;
            float a_i0 = s ? gi.y  : gi.x,  a_i1 = s ? gi1.y : gi1.x;
            float a_f0 = s ? gf.y  : gf.x,  a_f1 = s ? gf1.y : gf1.x;
            float a_g0 = s ? gg.y  : gg.x,  a_g1 = s ? gg1.y : gg1.x;
            float a_o0 = s ? go.y  : go.x,  a_o1 = s ? go1.y : go1.x;
            float cp0 = 0.0f, cp1 = 0.0f;
            if (t > 0) {
                int crow = g_srcC[k * BB + b];
                float2 cv = *(const float2*)&g_C[rb][(crow * BB + b) * DH + d0];
                cp0 = cv.x; cp1 = cv.y;
            }
            float ii0 = a_i0 + xb[0], ii1 = a_i1 + xb[1];
            float ff0 = a_f0 + xb[2], ff1 = a_f1 + xb[3];
            float gg0 = a_g0 + xb[4], gg1 = a_g1 + xb[5];
            float oo0 = a_o0 + xb[6], oo1 = a_o1 + xb[7];
            float c20 = sigm(ff0) * cp0 + sigm(ii0) * tanhf(gg0);
            float c21 = sigm(ff1) * cp1 + sigm(ii1) * tanhf(gg1);
            float h20 = sigm(oo0) * tanhf(c20);
            float h21 = sigm(oo1) * tanhf(c21);
            float2 ev = *(const float2*)&eps[(size_t)((t * KP + k) * BB + b) * DH + d0];
            h20 += ev.x * spv.x;
            h21 += ev.y * spv.y;
            int o = (k * BB + b) * DH + d0;
            *(float2*)&g_H[wb][o] = make_float2(h20, h21);
            *(float2*)&g_C[wb][o] = make_float2(c20, c21);
            pacc[2 * i + s] = h20 * fcd0 + h21 * fcd1;
            qacc[2 * i + s] = h20 * pw0 + h21 * pw1;
        }
    }
    // reduce over 64 threads (2 warps) sharing kq
#pragma unroll
    for (int i = 0; i < 8; i++) {
        float p = pacc[i], q = qacc[i];
        for (int off = 16; off; off >>= 1) {
            p += __shfl_down_sync(0xffffffffu, p, off);
            q += __shfl_down_sync(0xffffffffu, q, off);
        }
        if ((tid & 31) == 0) {
            red_p[kq * 8 + i][(tid >> 5) & 1] = p;
            red_q[kq * 8 + i][(tid >> 5) & 1] = q;
        }
    }
    __syncthreads();
    if (tid < KP) {
        g_proj[tid * BB + b]   = red_p[tid][0] + red_p[tid][1] + fcdb[0];
        g_pdfdot[tid * BB + b] = red_q[tid][0] + red_q[tid][1];
    }
}

// ---------------- K3: sort / weights / gumbel-max resample ----------------
__global__ void __launch_bounds__(1024) k3_resample(
        int t, const float* __restrict__ gumbel,
        const float* __restrict__ pdfW, const float* __restrict__ pdfb)
{
    int blk = blockIdx.x;          // 0..7 (32-b normalization groups)
    int tid = threadIdx.x;         // 1024
    __shared__ float proj_s[32][33];
    __shared__ int   order_s[32][33];
    __shared__ float lw_s[32][33];  // [b_local][slot]

    {   // load proj, store transposed
        int kk = tid >> 5, bb = tid & 31;
        proj_s[bb][kk] = g_proj[kk * BB + blk * 32 + bb];
    }
    __syncthreads();
    {   // stable ascending rank (matches jnp.argsort)
        int bl = tid >> 5, k = tid & 31;
        float v = proj_s[bl][k];
        int r = 0;
#pragma unroll
        for (int kp = 0; kp < 32; kp++) {
            float u = proj_s[bl][kp];
            r += (u < v) || (u == v && kp < k);
        }
        order_s[bl][r] = k;
    }
    __syncthreads();
    {   // weights per slot, normalized over the 32-b block; lw = log(w+1e-30)
        int slot = tid >> 5, bb = tid & 31;
        int bg = blk * 32 + bb;
        int k0 = order_s[bb][slot];
        float lp = g_pdfdot[k0 * BB + bg] + g_yt[bg] * pdfW[128] + pdfb[0];
        float v = expf(lp);
        float s = v;
        for (int off = 16; off; off >>= 1) s += __shfl_xor_sync(0xffffffffu, s, off);
        lw_s[bb][slot] = logf(v / s + 1e-30f);
    }
    __syncthreads();
    {   // gumbel argmax: warp handles p = warp_id; prefetch all 32 rows
        int p = tid >> 5, lane = tid & 31;
        const float* gbase = &gumbel[(((size_t)t * BB + blk * 32) * KP + p) * KP + lane];
        float gv[32];
#pragma unroll
        for (int it = 0; it < 32; it++)
            gv[it] = gbase[(size_t)it * KP * KP];
#pragma unroll
        for (int it = 0; it < 32; it++) {
            float v = lw_s[it][lane] + gv[it];
            int bi = lane;
            for (int off = 16; off; off >>= 1) {
                float ov = __shfl_down_sync(0xffffffffu, v, off);
                int  obi = __shfl_down_sync(0xffffffffu, bi, off);
                if (ov > v || (ov == v && obi < bi)) { v = ov; bi = obi; }
            }
            if (lane == 0) {
                int bg = blk * 32 + it;
                g_srcH[p * BB + bg] = order_s[it][bi];  // h sorted before selection
                g_srcC[p * BB + bg] = bi;               // c NOT sorted (torch quirk)
            }
        }
    }
}

// ---------------- K4: final projections -----------------------------------
__global__ void k4_out(const float* __restrict__ fcdW, const float* __restrict__ fcdb,
                       const float* __restrict__ fceW, const float* __restrict__ fceb,
                       float* __restrict__ out)
{
    int b = blockIdx.x * 8 + (threadIdx.x >> 5);
    int lane = threadIdx.x & 31;
    float a1 = 0.0f, a2 = 0.0f;
    for (int d = lane; d < 128; d += 32) {
        float hm = 0.0f;
        for (int p = 0; p < KP; p++) {
            int row = g_srcH[p * BB + b];
            hm += g_H[1][(row * BB + b) * DH + d];   // (T-1)&1 == 1
        }
        a1 += (hm * (1.0f / 32.0f)) * fcdW[d];
        a2 += g_ctx[b * 128 + d] * fceW[d];
    }
    for (int off = 16; off; off >>= 1) {
        a1 += __shfl_down_sync(0xffffffffu, a1, off);
        a2 += __shfl_down_sync(0xffffffffu, a2, off);
    }
    if (lane == 0) out[b] = a1 + fcdb[0] + a2 + fceb[0];
}

// ---------------- launch ---------------------------------------------------
extern "C" void kernel_launch(void* const* d_in, const int* in_sizes, int n_in,
                              void* d_out, int out_size)
{
    const float* enc   = (const float*)d_in[0];
    const float* yprev = (const float*)d_in[1];
    const float* eps   = (const float*)d_in[2];
    const float* gum   = (const float*)d_in[3];
    const float* W1    = (const float*)d_in[4];
    const float* b1    = (const float*)d_in[5];
    const float* W2    = (const float*)d_in[6];
    const float* b2    = (const float*)d_in[7];
    const float* Wih   = (const float*)d_in[8];
    const float* Whh   = (const float*)d_in[9];
    const float* bih   = (const float*)d_in[10];
    const float* bhh   = (const float*)d_in[11];
    const float* fcW   = (const float*)d_in[12];
    const float* fcb   = (const float*)d_in[13];
    const float* fcdW  = (const float*)d_in[14];
    const float* fcdb  = (const float*)d_in[15];
    const float* fceW  = (const float*)d_in[16];
    const float* fceb  = (const float*)d_in[17];
    const float* varW  = (const float*)d_in[18];
    const float* varb  = (const float*)d_in[19];
    const float* pdfW  = (const float*)d_in[20];
    const float* pdfb  = (const float*)d_in[21];
    float* out = (float*)d_out;

    k0_e1<<<BB, 256>>>(enc, W1, b1);
    for (int t = 0; t < TT; t++) {
        kA_step<<<BB, 256>>>(t, enc, yprev, W1, W2, b2, fcW, fcb, varW, varb,
                             Whh, Wih, bih, bhh, eps, fcdW, fcdb, pdfW);
        k3_resample<<<8, 1024>>>(t, gum, pdfW, pdfb);
    }
    k4_out<<<BB / 8, 256>>>(fcdW, fcdb, fceW, fceb, out);
}